// round 15
// baseline (speedup 1.0000x reference)
#include <cuda_runtime.h>
#include <cuda_fp16.h>
#include <math.h>
#include <stdint.h>

#define BATCH 1024
#define NAG   8
#define NDUM  16
#define PLAN  128
#define HID   256
#define TP    256      /* 2*PLAN  */
#define G3    768      /* 3*HID   */
#define TB    16384    /* NDUM*BATCH */
#define AD    16       /* agents*dirs */

/* ---------------- static device scratch (alloc-free rule) ---------------- */
__device__ float  g_comm[BATCH*NAG*PLAN];
__device__ int    g_mask[NAG*BATCH];
__device__ int    g_seq[BATCH];
__device__ int    g_packsrc[TB];
__device__ int    g_scatrank[TB];
__device__ __half g_cseq[(size_t)NAG*TB*TP];
__device__ __half g_gi[(size_t)NAG*TB*1536];
__device__ float  g_h[(size_t)AD*BATCH*HID];
__device__ __half g_h16[(size_t)AD*BATCH*HID];
__device__ __half g_out16[(size_t)AD*TB*HID];
__device__ __half g_sc16[(size_t)NAG*TB*512];
__device__ __half g_wi16[(size_t)NAG*1536*TP];
__device__ __half g_wh16[(size_t)AD*G3*HID];   /* row-reordered: row = 3*i + gate */
__device__ __half g_w116[(size_t)NAG*HID*512];

__device__ __forceinline__ uint32_t f2h2(float lo, float hi) {
    __half2 h = __floats2half2_rn(lo, hi);
    return *(uint32_t*)&h;
}
__device__ __forceinline__ void h4(const __half* p, float* f) {
    uint2 u = *(const uint2*)p;
    __half2 a = *(__half2*)&u.x, b = *(__half2*)&u.y;
    float2 fa = __half22float2(a), fb = __half22float2(b);
    f[0] = fa.x; f[1] = fa.y; f[2] = fb.x; f[3] = fb.y;
}

/* ---------------- setup: empty-check + comm select + mask + seq ---------------- */
__global__ void k_prep(const float* __restrict__ plans, const float* __restrict__ comm_plans) {
    int b = blockIdx.x;
    int tid = threadIdx.x, lane = tid & 31, w = tid >> 5;
    __shared__ int sred[8], smask[8], sempty;
    float4 cv = ((const float4*)(comm_plans + (size_t)b*1024))[tid];
    int nz = (cv.x!=0.f)||(cv.y!=0.f)||(cv.z!=0.f)||(cv.w!=0.f);
    unsigned ball = __ballot_sync(0xffffffffu, nz);
    if (lane == 0) sred[w] = (ball != 0);
    __syncthreads();
    if (tid == 0) {
        int e = 0;
        #pragma unroll
        for (int q = 0; q < 8; q++) e |= sred[q];
        sempty = !e;
    }
    __syncthreads();
    float4 pv = sempty ? ((const float4*)(plans + (size_t)b*1024))[tid] : cv;
    ((float4*)(g_comm + (size_t)b*1024))[tid] = pv;
    int nzz = (pv.x!=0.f)||(pv.y!=0.f)||(pv.z!=0.f)||(pv.w!=0.f);
    unsigned bm = __ballot_sync(0xffffffffu, nzz);
    if (lane == 0) { int m = (bm != 0); g_mask[w*BATCH + b] = m; smask[w] = m; }
    __syncthreads();
    if (tid == 0) {
        int s = 8;
        #pragma unroll
        for (int q = 0; q < 8; q++) s += smask[q];
        g_seq[b] = s;
    }
}

/* flat row-major rank matching for pack / scatter (torch masked semantics) */
__global__ void k_scan() {
    extern __shared__ int s_srclist[];        /* TB ints */
    __shared__ int wsm[16], wsp[16];
    __shared__ int sseq[BATCH];
    int tid = threadIdx.x;                    /* 512 */
    int lane = tid & 31, w = tid >> 5;
    sseq[tid] = g_seq[tid]; sseq[tid+512] = g_seq[tid+512];
    __syncthreads();
    int base = tid * 32;
    int cm = 0, cp = 0;
    int mk[32];
    if (tid < 256) {
        #pragma unroll
        for (int q = 0; q < 8; q++) {
            int4 mv = ((const int4*)g_mask)[tid*8 + q];
            mk[q*4+0]=mv.x; mk[q*4+1]=mv.y; mk[q*4+2]=mv.z; mk[q*4+3]=mv.w;
        }
    } else {
        #pragma unroll
        for (int q = 0; q < 32; q++) mk[q] = 1;
    }
    int tb = base >> 10;
    #pragma unroll
    for (int q = 0; q < 32; q++) {
        cm += mk[q];
        cp += (tb < sseq[(base + q) & 1023]);
    }
    int im = cm, ip = cp;
    #pragma unroll
    for (int o = 1; o < 32; o <<= 1) {
        int v = __shfl_up_sync(0xffffffffu, im, o); if (lane >= o) im += v;
        v     = __shfl_up_sync(0xffffffffu, ip, o); if (lane >= o) ip += v;
    }
    if (lane == 31) { wsm[w] = im; wsp[w] = ip; }
    __syncthreads();
    if (tid == 0) {
        int am = 0, ap = 0;
        for (int i = 0; i < 16; i++) {
            int t = wsm[i]; wsm[i] = am; am += t;
            t = wsp[i];     wsp[i] = ap; ap += t;
        }
    }
    __syncthreads();
    int rm = wsm[w] + im - cm;
    #pragma unroll
    for (int q = 0; q < 32; q++) {
        int j = base + q;
        if (mk[q]) { s_srclist[rm] = j; g_scatrank[j] = rm; rm++; }
        else       { g_scatrank[j] = -1; }
    }
    __syncthreads();
    int rp = wsp[w] + ip - cp;
    #pragma unroll
    for (int q = 0; q < 32; q++) {
        int j = base + q;
        if (tb < sseq[j & 1023]) { g_packsrc[j] = s_srclist[rp]; rp++; }
        else                     { g_packsrc[j] = -1; }
    }
}

/* fp32 -> fp16 weight conversion; Wh rows reordered to (3*i + gate) */
__global__ void k_wconv(const float* __restrict__ Wi_f, const float* __restrict__ Wi_b,
                        const float* __restrict__ Wh_f, const float* __restrict__ Wh_b,
                        const float* __restrict__ W1) {
    const size_t n_wi = (size_t)NAG*1536*TP/8;
    const size_t n_wh = (size_t)AD*G3*HID/8;
    const size_t n_w1 = (size_t)NAG*HID*512/8;
    size_t i8 = (size_t)blockIdx.x*256 + threadIdx.x;
    const float* src; __half* dst;
    if (i8 < n_wi) {
        size_t e = i8*8;
        int k = (int)(e & 255); size_t r = e >> 8;
        int g = (int)(r % 1536); int a = (int)(r / 1536);
        src = (g < G3) ? Wi_f + ((size_t)a*G3 + g)*TP + k
                       : Wi_b + ((size_t)a*G3 + g - G3)*TP + k;
        dst = g_wi16 + e;
    } else if (i8 < n_wi + n_wh) {
        size_t e = (i8 - n_wi)*8;
        int k = (int)(e & 255); size_t r = e >> 8;
        int nrow = (int)(r % G3); int z = (int)(r / G3);
        int ii = nrow / 3, gg = nrow % 3;               /* dest row 3*i+g <- src row g*HID+i */
        const float* W = (z & 1) ? Wh_b : Wh_f;
        src = W + ((size_t)(z >> 1)*G3 + gg*HID + ii)*HID + k;
        dst = g_wh16 + e;
    } else if (i8 < n_wi + n_wh + n_w1) {
        size_t e = (i8 - n_wi - n_wh)*8;
        src = W1 + e;
        dst = g_w116 + e;
    } else return;
    float4 v0 = ((const float4*)src)[0], v1 = ((const float4*)src)[1];
    uint4 o;
    o.x = f2h2(v0.x, v0.y); o.y = f2h2(v0.z, v0.w);
    o.z = f2h2(v1.x, v1.y); o.w = f2h2(v1.z, v1.w);
    *(uint4*)dst = o;
}

__global__ void k_hinit(const float* __restrict__ hx) {
    size_t idx = (size_t)blockIdx.x*256 + threadIdx.x;
    if (idx >= (size_t)AD*BATCH*HID/4) return;
    float4 v = ((const float4*)hx)[idx];
    ((float4*)g_h)[idx] = v;
    uint2 u; u.x = f2h2(v.x, v.y); u.y = f2h2(v.z, v.w);
    ((uint2*)g_h16)[idx] = u;
}

/* build packed sequence input per agent (gathers via pack_src), fp16 output */
__global__ void k_cseq(const float* __restrict__ plans, const float* __restrict__ dummy) {
    size_t idx = (size_t)blockIdx.x*256 + threadIdx.x;
    if (idx >= (size_t)NAG*TB*64) return;
    int c4 = (int)(idx & 63);
    size_t r = idx >> 6;
    int j = (int)(r % TB);
    int a = (int)(r / TB);
    float4 v = make_float4(0.f,0.f,0.f,0.f);
    int s = g_packsrc[j];
    if (s >= 0) {
        int t = s >> 10, b = s & 1023;
        if (t < NAG) {
            if (c4 < 32)
                v = ((const float4*)(plans + (size_t)(b*NAG + a)*PLAN))[c4];
            else
                v = ((const float4*)(g_comm + (size_t)(b*NAG + t)*PLAN))[c4 - 32];
        } else {
            v = ((const float4*)(dummy + ((size_t)(a*(NDUM-NAG) + (t - NAG))*BATCH + b)*TP))[c4];
        }
    }
    uint2 u;
    u.x = f2h2(v.x, v.y);
    u.y = f2h2(v.z, v.w);
    *(uint2*)(g_cseq + ((size_t)a*TB + j)*TP + c4*4) = u;
}

/* ---------------- fp16 GEMM, cp.async 3-stage pipeline (NT), templated mode ------
   MODE 0: gi = cseq @ wi16^T  (M=16384,N=1536,K=256, z=agent)  -> fp16
   MODE 1: gh tile + fused GRU gate epilogue (M=1024,N=192-tiles of 3i+g, K=256)
   MODE 2: cm = (relu(sc16 @ w116^T + b1)) @ W2^T + b2 fused -> fp32 out
   BM=128; BN=256/192/256; 8 warps (2m x 4n). */
#define SA_STRIDE 20
#define SB_OFF    2560            /* 128*20 */

#define CP16(dst, src) asm volatile("cp.async.cg.shared.global [%0], [%1], 16;" :: "r"(dst), "l"(src))
#define CP_COMMIT()    asm volatile("cp.async.commit_group;" ::: "memory")
#define CP_WAIT1()     asm volatile("cp.async.wait_group 1;" ::: "memory")
#define CP_WAIT0()     asm volatile("cp.async.wait_group 0;" ::: "memory")

template<int MODE>
__global__ void __launch_bounds__(256) gemm_fp16(int t, const float* __restrict__ b1,
        const float* __restrict__ W2, const float* __restrict__ b2, float* __restrict__ outc) {
    constexpr int BN  = (MODE == 1) ? 192 : 256;
    constexpr int NJ  = (MODE == 1) ? 6 : 8;
    constexpr int WN  = (MODE == 1) ? 48 : 64;
    constexpr int K   = (MODE == 2) ? 512 : 256;
    constexpr int STAGE = SB_OFF + BN*SA_STRIDE;
    extern __shared__ uint32_t dsm[];
    const __half* A; const __half* B;
    __half* Ch = 0; const float* bias = 0;
    int Nd = 0;
    const int zb = blockIdx.z;
    if (MODE == 0) {
        A = g_cseq + (size_t)zb*TB*TP;    B = g_wi16 + (size_t)zb*1536*TP;
        Ch = g_gi + (size_t)zb*TB*1536;   Nd = 1536;
    } else if (MODE == 1) {
        A = g_h16 + (size_t)zb*BATCH*HID; B = g_wh16 + (size_t)zb*G3*HID;
    } else {
        A = g_sc16 + (size_t)zb*TB*512;   B = g_w116 + (size_t)zb*HID*512;
        bias = b1 + zb*HID;               Nd = 256;
    }
    const int m0 = blockIdx.y * 128;
    const int n0 = blockIdx.x * BN;
    const int tid = threadIdx.x, lane = tid & 31, warp = tid >> 5;
    const int wm = (warp & 1) << 6, wn = (warp >> 1) * WN;
    const int kr = lane & 3, rg = lane >> 2;

    /* loaders: A — 2 threads/row, 32B each; B — 1 thread/row, 64B */
    const int lm = tid >> 1, lkh = tid & 1;
    const __half* gA = A + (size_t)(m0 + lm)*K + lkh*16;
    const __half* gB = B + (size_t)(n0 + tid)*K;
    uint32_t smb = (uint32_t)__cvta_generic_to_shared(dsm);
    const uint32_t dA = smb + (uint32_t)(lm*SA_STRIDE + lkh*8)*4;
    const uint32_t dB = smb + (uint32_t)(SB_OFF + tid*SA_STRIDE)*4;

#define ISSUE(kt, s) do {                                     \
    uint32_t so = (uint32_t)(s)*STAGE*4;                      \
    const __half* pa = gA + (size_t)(kt)*32;                  \
    CP16(dA + so,      pa);                                   \
    CP16(dA + so + 16, pa + 8);                               \
    if (BN == 256 || tid < BN) {                              \
        const __half* pb = gB + (size_t)(kt)*32;              \
        CP16(dB + so,      pb);                               \
        CP16(dB + so + 16, pb + 8);                           \
        CP16(dB + so + 32, pb + 16);                          \
        CP16(dB + so + 48, pb + 24);                          \
    }                                                         \
} while (0)

    float acc[4][NJ][4];
    #pragma unroll
    for (int i = 0; i < 4; i++)
        #pragma unroll
        for (int j = 0; j < NJ; j++)
            #pragma unroll
            for (int q = 0; q < 4; q++) acc[i][j][q] = 0.f;

    const int nk = K >> 5;
    ISSUE(0, 0); CP_COMMIT();
    ISSUE(1, 1); CP_COMMIT();

    for (int kt = 0; kt < nk; kt++) {
        CP_WAIT1();
        __syncthreads();
        if (kt + 2 < nk) ISSUE(kt + 2, (kt + 2) % 3);
        CP_COMMIT();
        const uint32_t* SAs = dsm + (kt % 3)*STAGE;
        const uint32_t* SBs = SAs + SB_OFF;
        #pragma unroll
        for (int cc = 0; cc < 2; cc++) {
            const int kb = cc*8 + kr;
            uint32_t bf[NJ][2];
            #pragma unroll
            for (int j = 0; j < NJ; j++) {
                bf[j][0] = SBs[(wn + 8*j + rg)*SA_STRIDE + kb];
                bf[j][1] = SBs[(wn + 8*j + rg)*SA_STRIDE + kb + 4];
            }
            #pragma unroll
            for (int i = 0; i < 4; i++) {
                const int r = wm + 16*i + rg;
                uint32_t a0 = SAs[ r      *SA_STRIDE + kb];
                uint32_t a1 = SAs[(r + 8) *SA_STRIDE + kb];
                uint32_t a2 = SAs[ r      *SA_STRIDE + kb + 4];
                uint32_t a3 = SAs[(r + 8) *SA_STRIDE + kb + 4];
                #pragma unroll
                for (int j = 0; j < NJ; j++) {
                    asm volatile(
                        "mma.sync.aligned.m16n8k16.row.col.f32.f16.f16.f32 "
                        "{%0,%1,%2,%3},{%4,%5,%6,%7},{%8,%9},{%0,%1,%2,%3};"
                        : "+f"(acc[i][j][0]), "+f"(acc[i][j][1]),
                          "+f"(acc[i][j][2]), "+f"(acc[i][j][3])
                        : "r"(a0), "r"(a1), "r"(a2), "r"(a3),
                          "r"(bf[j][0]), "r"(bf[j][1]));
                }
            }
        }
    }
#undef ISSUE

    if (MODE == 0) {
        const int cb = kr << 1;
        #pragma unroll
        for (int i = 0; i < 4; i++) {
            #pragma unroll
            for (int j = 0; j < NJ; j++) {
                int r0 = m0 + wm + 16*i + rg;
                int c  = n0 + wn + 8*j + cb;
                *(__half2*)(Ch + (size_t)r0*Nd + c)     = __floats2half2_rn(acc[i][j][0], acc[i][j][1]);
                *(__half2*)(Ch + (size_t)(r0+8)*Nd + c) = __floats2half2_rn(acc[i][j][2], acc[i][j][3]);
            }
        }
    } else if (MODE == 1) {
        /* -------- fused GRU gate epilogue -------- */
        CP_WAIT0();
        __syncthreads();
        /* store gh tile to smem as half2 words: [row][col/2], stride 100 words */
        #pragma unroll
        for (int i = 0; i < 4; i++) {
            #pragma unroll
            for (int j = 0; j < NJ; j++) {
                int r0 = wm + 16*i + rg;
                int cw = (wn + 8*j + (kr << 1)) >> 1;
                dsm[ r0     *100 + cw] = f2h2(acc[i][j][0], acc[i][j][1]);
                dsm[(r0 + 8)*100 + cw] = f2h2(acc[i][j][2], acc[i][j][3]);
            }
        }
        __syncthreads();
        const int row = tid >> 1, half = tid & 1;
        const int b = m0 + row;
        const int sl = g_seq[b];
        if (t < sl) {
            const int a = zb >> 1, d = zb & 1;
            const int ot = d ? (sl - 1 - t) : t;
            const __half* gi = g_gi + ((size_t)a*TB + (size_t)ot*BATCH + b)*1536 + d*G3;
            #pragma unroll
            for (int q = 0; q < 8; q++) {
                const int di = half*32 + 4*q;               /* local hidden idx 0..63 */
                const int ig = blockIdx.x*64 + di;          /* global hidden idx */
                /* gh triples from smem: 12 halves = 6 words at row*100 + 3*di/2 */
                const uint32_t* wv = &dsm[row*100 + ((3*di) >> 1)];
                float gh12[12];
                #pragma unroll
                for (int e = 0; e < 6; e++) {
                    float2 fp = __half22float2(*(const __half2*)&wv[e]);
                    gh12[2*e] = fp.x; gh12[2*e+1] = fp.y;
                }
                float gir[4], giz[4], gin[4];
                h4(gi + ig,        gir);
                h4(gi + HID + ig,  giz);
                h4(gi + 2*HID + ig, gin);
                size_t hb = ((size_t)zb*BATCH + b)*HID + ig;
                float4 hv = *(const float4*)(g_h + hb);
                float hvv[4] = {hv.x, hv.y, hv.z, hv.w};
                float hn[4];
                #pragma unroll
                for (int e = 0; e < 4; e++) {
                    float rr = 1.f/(1.f + expf(-(gir[e] + gh12[3*e + 0])));
                    float zz = 1.f/(1.f + expf(-(giz[e] + gh12[3*e + 1])));
                    float nn = tanhf(gin[e] + rr*gh12[3*e + 2]);
                    hn[e] = (1.f - zz)*nn + zz*hvv[e];
                }
                *(float4*)(g_h + hb) = make_float4(hn[0], hn[1], hn[2], hn[3]);
                uint2 u; u.x = f2h2(hn[0], hn[1]); u.y = f2h2(hn[2], hn[3]);
                *(uint2*)(g_h16 + hb) = u;
                *(uint2*)(g_out16 + ((size_t)zb*TB + (size_t)ot*BATCH + b)*HID + ig) = u;
                /* final hidden states live in d_out; last update per (z,b) is at t=sl-1 */
                *(float4*)(outc + (size_t)NAG*NDUM*BATCH*2 + hb) = make_float4(hn[0], hn[1], hn[2], hn[3]);
            }
        }
    } else {
        /* fused: h1 = relu(acc + b1); cm = h1 @ W2^T + b2 */
        const int cb = kr << 1;
        const float* w2a = W2 + (size_t)zb*512;
        const float* w2b = w2a + 256;
        float pr[4][2][2];
        #pragma unroll
        for (int i = 0; i < 4; i++)
            #pragma unroll
            for (int r2 = 0; r2 < 2; r2++) { pr[i][r2][0] = 0.f; pr[i][r2][1] = 0.f; }
        #pragma unroll
        for (int i = 0; i < 4; i++) {
            #pragma unroll
            for (int j = 0; j < NJ; j++) {
                int c = wn + 8*j + cb;           /* n0 == 0 */
                float bb0 = bias[c], bb1 = bias[c+1];
                float v0 = fmaxf(acc[i][j][0] + bb0, 0.f);
                float v1 = fmaxf(acc[i][j][1] + bb1, 0.f);
                float v2 = fmaxf(acc[i][j][2] + bb0, 0.f);
                float v3 = fmaxf(acc[i][j][3] + bb1, 0.f);
                float wa0 = __ldg(w2a + c), wa1 = __ldg(w2a + c + 1);
                float wb0 = __ldg(w2b + c), wb1 = __ldg(w2b + c + 1);
                pr[i][0][0] += v0*wa0 + v1*wa1;
                pr[i][0][1] += v0*wb0 + v1*wb1;
                pr[i][1][0] += v2*wa0 + v3*wa1;
                pr[i][1][1] += v2*wb0 + v3*wb1;
            }
        }
        #pragma unroll
        for (int i = 0; i < 4; i++)
            #pragma unroll
            for (int r2 = 0; r2 < 2; r2++)
                #pragma unroll
                for (int o = 0; o < 2; o++) {
                    float x = pr[i][r2][o];
                    x += __shfl_xor_sync(0xffffffffu, x, 1);
                    x += __shfl_xor_sync(0xffffffffu, x, 2);
                    pr[i][r2][o] = x;
                }
        CP_WAIT0();
        __syncthreads();
        float* psm = (float*)dsm;                 /* 128 rows x 2 outputs */
        if (tid < 256) psm[tid] = 0.f;
        __syncthreads();
        if (kr == 0) {
            #pragma unroll
            for (int i = 0; i < 4; i++)
                #pragma unroll
                for (int r2 = 0; r2 < 2; r2++) {
                    int row = wm + 16*i + rg + 8*r2;
                    atomicAdd(&psm[row*2 + 0], pr[i][r2][0]);
                    atomicAdd(&psm[row*2 + 1], pr[i][r2][1]);
                }
        }
        __syncthreads();
        if (tid < 256) {
            int row = tid >> 1, o = tid & 1;
            outc[((size_t)zb*TB + m0 + row)*2 + o] = psm[tid] + b2[zb*2 + o];
        }
    }
}

/* ---------------- scatter + LayerNorm (fp16 in, fp16 out) ---------------- */
__global__ void k_scatln(const float* __restrict__ gamma, const float* __restrict__ beta) {
    int j = blockIdx.x, a = blockIdx.y;
    int tid = threadIdx.x;
    int c = tid * 4;
    float v0 = 0.f, v1 = 0.f, v2 = 0.f, v3 = 0.f;
    int msk = (j >= NAG*BATCH) ? 1 : g_mask[j];
    if (msk) {
        int r = g_scatrank[j];
        int d  = (c >= HID) ? 1 : 0;
        int cc = d ? c - HID : c;
        float f[4];
        h4(g_out16 + ((size_t)(a*2 + d)*TB + r)*HID + cc, f);
        v0 = f[0]; v1 = f[1]; v2 = f[2]; v3 = f[3];
    }
    __shared__ float red[128];
    red[tid] = v0 + v1 + v2 + v3;
    __syncthreads();
    for (int st = 64; st > 0; st >>= 1) { if (tid < st) red[tid] += red[tid+st]; __syncthreads(); }
    float mu = red[0] * (1.f/512.f);
    __syncthreads();
    float d0 = v0-mu, d1 = v1-mu, d2 = v2-mu, d3 = v3-mu;
    red[tid] = d0*d0 + d1*d1 + d2*d2 + d3*d3;
    __syncthreads();
    for (int st = 64; st > 0; st >>= 1) { if (tid < st) red[tid] += red[tid+st]; __syncthreads(); }
    float rstd = rsqrtf(red[0]*(1.f/512.f) + 1e-5f);
    float4 gg = ((const float4*)(gamma + (size_t)a*512))[tid];
    float4 bb = ((const float4*)(beta  + (size_t)a*512))[tid];
    float o0 = d0*rstd*gg.x + bb.x;
    float o1 = d1*rstd*gg.y + bb.y;
    float o2 = d2*rstd*gg.z + bb.z;
    float o3 = d3*rstd*gg.w + bb.w;
    uint2 u; u.x = f2h2(o0, o1); u.y = f2h2(o2, o3);
    *(uint2*)(g_sc16 + ((size_t)a*TB + j)*512 + c) = u;
}

/* ---------------- launcher ---------------- */
#define SMEM_M0 ((SB_OFF + 256*SA_STRIDE)*3*4)
#define SMEM_M1 ((SB_OFF + 192*SA_STRIDE)*3*4)
#define SMEM_M2 ((SB_OFF + 256*SA_STRIDE)*3*4)

extern "C" void kernel_launch(void* const* d_in, const int* in_sizes, int n_in,
                              void* d_out, int out_size) {
    const float* plans      = (const float*)d_in[0];
    const float* comm_plans = (const float*)d_in[1];
    const float* hx         = (const float*)d_in[2];
    const float* dummy      = (const float*)d_in[3];
    const float* Wi_f       = (const float*)d_in[4];
    const float* Wh_f       = (const float*)d_in[5];
    const float* Wi_b       = (const float*)d_in[6];
    const float* Wh_b       = (const float*)d_in[7];
    const float* ln_g       = (const float*)d_in[8];
    const float* ln_b       = (const float*)d_in[9];
    const float* W1         = (const float*)d_in[10];
    const float* b1         = (const float*)d_in[11];
    const float* W2         = (const float*)d_in[12];
    const float* b2         = (const float*)d_in[13];
    float* out = (float*)d_out;

    cudaFuncSetAttribute(k_scan, cudaFuncAttributeMaxDynamicSharedMemorySize, TB*4);
    cudaFuncSetAttribute(gemm_fp16<0>, cudaFuncAttributeMaxDynamicSharedMemorySize, SMEM_M0);
    cudaFuncSetAttribute(gemm_fp16<1>, cudaFuncAttributeMaxDynamicSharedMemorySize, SMEM_M1);
    cudaFuncSetAttribute(gemm_fp16<2>, cudaFuncAttributeMaxDynamicSharedMemorySize, SMEM_M2);

    k_prep<<<BATCH, 256>>>(plans, comm_plans);
    k_scan<<<1, 512, TB*4>>>();
    k_wconv<<<3584, 256>>>(Wi_f, Wi_b, Wh_f, Wh_b, W1);
    k_cseq<<<(NAG*TB*64 + 255)/256, 256>>>(plans, dummy);
    k_hinit<<<(AD*BATCH*HID/4 + 255)/256, 256>>>(hx);

    /* input projections */
    {
        dim3 g(1536/256, TB/128, NAG);
        gemm_fp16<0><<<g, 256, SMEM_M0>>>(0, b1, W2, b2, out);
    }

    /* 16 recurrent steps: gh GEMM with fused gate epilogue (writes h + out hxs) */
    for (int t = 0; t < NDUM; t++) {
        dim3 g(4, BATCH/128, AD);
        gemm_fp16<1><<<g, 256, SMEM_M1>>>(t, b1, W2, b2, out);
    }

    /* scatter + LayerNorm -> fp16 scores */
    {
        dim3 g(TB, NAG);
        k_scatln<<<g, 128>>>(ln_g, ln_b);
    }

    /* MLP layer 1 + final projection fused -> coord_masks */
    {
        dim3 g(1, TB/128, NAG);
        gemm_fp16<2><<<g, 256, SMEM_M2>>>(0, b1, W2, b2, out);
    }
}